// round 15
// baseline (speedup 1.0000x reference)
#include <cuda_runtime.h>
#include <cstdint>
#include <cstddef>

#define BATCH 64
#define TSTEPS 2000
#define HID 512
#define NB 4      // batches per CTA
#define NJC 64    // hidden outputs per CTA (lane covers 2 j)
#define NW 16     // warps per CTA (512 threads)
#define KW 32     // k-range per warp (single producer jg' = w>>1)
#define GJ 8      // j groups (grid.x) -> ring of 8
#define GB 16     // batch groups (grid.y)
#define NEXC 409  // int(0.8*512)
#define GJP 16    // output partials per (b,t): 8 jgs x 2 halves

#define ALPHA_F 0.1f
#define IN_SCALE_F 0.004472135954999579f
#define REC_SCALE_F 0.044721359549995794f

// ---------------- device globals (scratch; no allocation allowed) -------------
__device__ float g_h[2][BATCH * HID];              // double-buffered relu(h) state
__device__ unsigned g_flag[GB][GJ][32];            // per-(bg,jg) flag, 128B padded
__device__ float g_opart[(size_t)BATCH * TSTEPS * GJP]; // output partials [b][t][p]

// ---------------- JAX threefry2x32 ----------------
__device__ __forceinline__ void tf2x32(uint32_t k0, uint32_t k1,
                                       uint32_t x0, uint32_t x1,
                                       uint32_t& o0, uint32_t& o1) {
    uint32_t kx = k0 ^ k1 ^ 0x1BD11BDAu;
    x0 += k0; x1 += k1;
#define TFR(r) { x0 += x1; x1 = __funnelshift_l(x1, x1, r); x1 ^= x0; }
    TFR(13) TFR(15) TFR(26) TFR(6)   x0 += k1; x1 += kx + 1u;
    TFR(17) TFR(29) TFR(16) TFR(24)  x0 += kx; x1 += k0 + 2u;
    TFR(13) TFR(15) TFR(26) TFR(6)   x0 += k0; x1 += k1 + 3u;
    TFR(17) TFR(29) TFR(16) TFR(24)  x0 += k1; x1 += kx + 4u;
    TFR(13) TFR(15) TFR(26) TFR(6)   x0 += kx; x1 += k0 + 5u;
#undef TFR
    o0 = x0; o1 = x1;
}

// XLA f32 ErfInv (Giles)
__device__ __forceinline__ float erfinv_xla(float x) {
    float w = -log1pf(-x * x);
    float p;
    if (w < 5.f) {
        w -= 2.5f;
        p = 2.81022636e-08f;
        p = fmaf(p, w, 3.43273939e-07f);
        p = fmaf(p, w, -3.5233877e-06f);
        p = fmaf(p, w, -4.39150654e-06f);
        p = fmaf(p, w, 0.00021858087f);
        p = fmaf(p, w, -0.00125372503f);
        p = fmaf(p, w, -0.00417768164f);
        p = fmaf(p, w, 0.246640727f);
        p = fmaf(p, w, 1.50140941f);
    } else {
        w = sqrtf(w) - 3.f;
        p = -0.000200214257f;
        p = fmaf(p, w, 0.000100950558f);
        p = fmaf(p, w, 0.00134934322f);
        p = fmaf(p, w, -0.00367342844f);
        p = fmaf(p, w, 0.00573950773f);
        p = fmaf(p, w, -0.0076224613f);
        p = fmaf(p, w, 0.00943887047f);
        p = fmaf(p, w, 1.00167406f);
        p = fmaf(p, w, 2.83297682f);
    }
    return p * x;
}

__device__ __forceinline__ float jax_normal(uint32_t k0, uint32_t k1, uint32_t idx) {
    uint32_t o0, o1;
    tf2x32(k0, k1, 0u, idx, o0, o1);
    uint32_t bits = o0 ^ o1;
    float f = __uint_as_float((bits >> 9) | 0x3f800000u) - 1.0f;
    const float lo = -0.99999994f;   // nextafter(-1,0)
    float val = fmaxf(fmaf(f, 2.0f, lo), lo);
    return 1.4142135623730951f * erfinv_xla(val);
}

// ---------------- sync primitives ----------------
__device__ __forceinline__ void st_release(unsigned* p, unsigned v) {
    asm volatile("st.release.gpu.global.u32 [%0], %1;" :: "l"(p), "r"(v) : "memory");
}
__device__ __forceinline__ unsigned ld_acquire(const unsigned* p) {
    unsigned v;
    asm volatile("ld.acquire.gpu.global.u32 %0, [%1];" : "=r"(v) : "l"(p) : "memory");
    return v;
}

// ---------------- main persistent RNN kernel ----------------
__global__ void __launch_bounds__(512, 1)
rnn_main(const float* __restrict__ i_stim, const float* __restrict__ i_cc,
         const float* __restrict__ hidden, const float* __restrict__ w_ih,
         const float* __restrict__ w_hh, const float* __restrict__ b_hh,
         const float* __restrict__ w_ho,
         float* __restrict__ hids) {
    __shared__ __align__(16) float rh_s[NW][NB][KW];  // per-warp staged slices (8 KB)
    __shared__ float red_s[2][NW][NB][NJC];           // double-buffered partials (32 KB)
    __shared__ float cur_s[2][NB][2];                 // relu(x + in-noise)

    const int tid = threadIdx.x;
    const int w = tid >> 5, l = tid & 31;
    const int jg = blockIdx.x, bg = blockIdx.y;
    const int J0 = jg * NJC, B0 = bg * NB;
    // GEMM role: lane l covers j1 = J0+l, j2 = J0+32+l over k-range [32w, 32w+32)
    const int j1 = J0 + l, j2 = J0 + 32 + l;
    const int k0 = w * KW;
    // epilogue role (warps 0-7 only): (batch = w>>1, j = (w&1)*32 + l)
    const bool epi = (w < 8);
    const int be = (w >> 1) & 3, jl = ((w & 1) << 5) + l;
    const int bglob = B0 + be, jglob = J0 + jl;

    uint32_t kin0, kin1, krec0, krec1;
    tf2x32(0u, 42u, 0u, 0u, kin0, kin1);
    tf2x32(0u, 42u, 0u, 1u, krec0, krec1);

    // Time-invariant W_ei chunks for the lane's two j rows, packed f32x2:
    // w_ei[j][k] = abs(w_hh[j][k]) * (k==j ? 0 : (k<409 ? +1 : -1))
    unsigned long long wpa[KW / 2], wpb[KW / 2];
#pragma unroll
    for (int i = 0; i < KW / 2; i++) {
        int k = k0 + 2 * i;
        float a0 = fabsf(w_hh[j1 * HID + k]);
        float a1 = fabsf(w_hh[j1 * HID + k + 1]);
        float b0 = fabsf(w_hh[j2 * HID + k]);
        float b1 = fabsf(w_hh[j2 * HID + k + 1]);
        if (k == j1) a0 = 0.f;
        if (k + 1 == j1) a1 = 0.f;
        if (k == j2) b0 = 0.f;
        if (k + 1 == j2) b1 = 0.f;
        if (k >= NEXC) { a0 = -a0; b0 = -b0; }
        if (k + 1 >= NEXC) { a1 = -a1; b1 = -b1; }
        asm("mov.b64 %0, {%1, %2};" : "=l"(wpa[i]) : "f"(a0), "f"(a1));
        asm("mov.b64 %0, {%1, %2};" : "=l"(wpb[i]) : "f"(b0), "f"(b1));
    }

    const float wih0 = epi ? w_ih[jglob * 2] : 0.f;
    const float wih1 = epi ? w_ih[jglob * 2 + 1] : 0.f;
    const float bhh  = epi ? b_hh[jglob] : 0.f;
    const float who  = epi ? w_ho[jglob] : 0.f;
    float hreg = epi ? hidden[bglob * HID + jglob] : 0.f;

    // publish relu(h0) into buffer 0, then announce
    if (epi) __stcg(&g_h[0][bglob * HID + jglob], fmaxf(hreg, 0.f));
    __syncthreads();
    if (tid == 0) st_release(&g_flag[bg][jg][0], 1u);

    // per-warp poll: ONE producer CTA (jg' = w>>1); lane 0 polls
    const unsigned* fpoll = &g_flag[bg][w >> 1][0];
    // staging role: lane l -> (b = l>>3, float4 col = l&7); 4b x 8cols = 32 lanes
    const int sb = l >> 3, sc = l & 7;

    for (int t = 0; t < TSTEPS; t++) {
        const int rb = t & 1, wb = rb ^ 1;
        const unsigned tgt = (unsigned)(t + 1);

        // --- epilogue-only independent work (GEMM warps skip straight to poll) ---
        float nr = 0.f;
        if (epi) nr = jax_normal(krec0, krec1,
                                 (uint32_t)((t * BATCH + bglob) * HID + jglob));
        if (tid < NB * 2) {
            int bb = tid >> 1, ii = tid & 1;
            int bB = B0 + bb;
            float x = (ii == 0 ? i_stim : i_cc)[bB * TSTEPS + t];
            float n = jax_normal(kin0, kin1, (uint32_t)((t * BATCH + bB) * 2 + ii));
            cur_s[rb][bb][ii] = fmaxf(fmaf(IN_SCALE_F, n, x), 0.f);
        }

        // --- per-warp wait on THIS warp's single producer CTA ---
        for (;;) {
            unsigned v = (l == 0) ? ld_acquire(fpoll) : tgt;
            if (__all_sync(0xffffffffu, v >= tgt)) break;
        }

        // --- stage this warp's slice (already relu'd by producers): 4b x 32k ---
        {
            const float* src = &g_h[rb][B0 * HID + k0];
            float4 v = __ldcg((const float4*)(src + sb * HID + sc * 4));
            *(float4*)&rh_s[w][sb][sc * 4] = v;
        }
        __syncwarp();

        // --- GEMM partials: each rh load feeds BOTH j rows (2x FMA per LDS) ---
        unsigned long long acc2a[NB], acc2b[NB];
#pragma unroll
        for (int b = 0; b < NB; b++) { acc2a[b] = 0ull; acc2b[b] = 0ull; }
#pragma unroll
        for (int kk = 0; kk < KW; kk += 4) {
            const unsigned long long wa01 = wpa[kk / 2];
            const unsigned long long wa23 = wpa[kk / 2 + 1];
            const unsigned long long wb01 = wpb[kk / 2];
            const unsigned long long wb23 = wpb[kk / 2 + 1];
#pragma unroll
            for (int b = 0; b < NB; b++) {
                unsigned long long r01, r23;
                uint32_t a = (uint32_t)__cvta_generic_to_shared(&rh_s[w][b][kk]);
                asm("ld.shared.v2.u64 {%0, %1}, [%2];"
                    : "=l"(r01), "=l"(r23) : "r"(a));   // broadcast LDS.128
                asm("fma.rn.f32x2 %0, %1, %2, %0;" : "+l"(acc2a[b]) : "l"(r01), "l"(wa01));
                asm("fma.rn.f32x2 %0, %1, %2, %0;" : "+l"(acc2a[b]) : "l"(r23), "l"(wa23));
                asm("fma.rn.f32x2 %0, %1, %2, %0;" : "+l"(acc2b[b]) : "l"(r01), "l"(wb01));
                asm("fma.rn.f32x2 %0, %1, %2, %0;" : "+l"(acc2b[b]) : "l"(r23), "l"(wb23));
            }
        }
#pragma unroll
        for (int b = 0; b < NB; b++) {
            float lo, hi;
            asm("mov.b64 {%0, %1}, %2;" : "=f"(lo), "=f"(hi) : "l"(acc2a[b]));
            red_s[rb][w][b][l] = lo + hi;
            asm("mov.b64 {%0, %1}, %2;" : "=f"(lo), "=f"(hi) : "l"(acc2b[b]));
            red_s[rb][w][b][32 + l] = lo + hi;
        }
        __syncthreads();   // sync #1: red handoff (full block)

        if (epi) {
            // --- epilogue: integrate h for (bglob, jglob) ---
            float s = 0.f;
#pragma unroll
            for (int ww = 0; ww < NW; ww++) s += red_s[rb][ww][be][jl];
            float hid_in  = fmaf(cur_s[rb][be][0], wih0, cur_s[rb][be][1] * wih1);
            float hid_hid = s + bhh + REC_SCALE_F * nr;
            float h = hreg;
            float hn = fmaf(hid_in + hid_hid - h, ALPHA_F, h);
            hreg = hn;
            __stcg(&g_h[wb][bglob * HID + jglob], fmaxf(hn, 0.f));
            asm volatile("bar.sync 1, 256;" ::: "memory");   // epilogue warps only
            if (tid == 0) st_release(&g_flag[bg][jg][0], (unsigned)(t + 2));

            // --- off-critical-path stores (after release) ---
            __stcs(&hids[(size_t)bglob * (TSTEPS * HID) + (size_t)t * HID + jglob], hn);
            float op = fmaxf(hn, 0.f) * who;
#pragma unroll
            for (int o = 16; o; o >>= 1) op += __shfl_down_sync(0xffffffffu, op, o);
            if (l == 0)
                g_opart[((size_t)bglob * TSTEPS + t) * GJP + jg * 2 + (w & 1)] = op;
        }
    }
}

// ---------------- output: sum 16 partials + bias ----------------
__global__ void out_kernel(const float* __restrict__ b_ho, float* __restrict__ outs) {
    int i = blockIdx.x * blockDim.x + threadIdx.x;   // i = b*T + t
    if (i >= BATCH * TSTEPS) return;
    const float4* p = (const float4*)&g_opart[(size_t)i * GJP];
    float s = 0.f;
#pragma unroll
    for (int q = 0; q < GJP / 4; q++) {
        float4 v = p[q];
        s += (v.x + v.y) + (v.z + v.w);
    }
    outs[i] = s + b_ho[0];
}

// ---------------- launch ----------------
extern "C" void kernel_launch(void* const* d_in, const int* in_sizes, int n_in,
                              void* d_out, int out_size) {
    const float* i_stim = (const float*)d_in[0];
    const float* i_cc   = (const float*)d_in[1];
    const float* hidden = (const float*)d_in[2];
    const float* w_ih   = (const float*)d_in[3];
    // d_in[4] = b_ih — never used by the reference (faithful to source)
    const float* w_hh   = (const float*)d_in[5];
    const float* b_hh   = (const float*)d_in[6];
    const float* w_ho   = (const float*)d_in[7];
    const float* b_ho   = (const float*)d_in[8];

    float* outs = (float*)d_out;                 // [B,T,1]
    float* hids = outs + (size_t)BATCH * TSTEPS; // [B,T,H]

    void* flagp = nullptr;
    cudaGetSymbolAddress(&flagp, g_flag);
    cudaMemsetAsync(flagp, 0, sizeof(unsigned) * GB * GJ * 32);

    dim3 grid(GJ, GB);
    rnn_main<<<grid, 512>>>(i_stim, i_cc, hidden, w_ih, w_hh, b_hh, w_ho, hids);

    int blocks = (BATCH * TSTEPS + 255) / 256;
    out_kernel<<<blocks, 256>>>(b_ho, outs);
}

// round 16
// speedup vs baseline: 1.7334x; 1.7334x over previous
#include <cuda_runtime.h>
#include <cstdint>
#include <cstddef>

#define BATCH 64
#define TSTEPS 2000
#define HID 512
#define NB 4      // batches per CTA
#define NJC 64    // hidden outputs per CTA (lane covers 2 j)
#define NW 8      // warps per CTA
#define KW 64     // k-range per warp (aligns with ONE producer jg)
#define GJ 8      // j groups (grid.x) -> ring of 8
#define GB 16     // batch groups (grid.y)
#define NEXC 409  // int(0.8*512)
#define GJP 16    // output partials per (b,t): 8 jgs x 2 halves

#define ALPHA_F 0.1f
#define IN_SCALE_F 0.004472135954999579f
#define REC_SCALE_F 0.044721359549995794f

// ---------------- device globals (scratch; no allocation allowed) -------------
__device__ float g_h[2][BATCH * HID];              // double-buffered relu(h) state
__device__ unsigned g_flag[GB][GJ][32];            // per-(bg,jg) flag, 128B padded
__device__ float g_opart[(size_t)BATCH * TSTEPS * GJP]; // output partials [b][t][p]

// ---------------- JAX threefry2x32 ----------------
__device__ __forceinline__ void tf2x32(uint32_t k0, uint32_t k1,
                                       uint32_t x0, uint32_t x1,
                                       uint32_t& o0, uint32_t& o1) {
    uint32_t kx = k0 ^ k1 ^ 0x1BD11BDAu;
    x0 += k0; x1 += k1;
#define TFR(r) { x0 += x1; x1 = __funnelshift_l(x1, x1, r); x1 ^= x0; }
    TFR(13) TFR(15) TFR(26) TFR(6)   x0 += k1; x1 += kx + 1u;
    TFR(17) TFR(29) TFR(16) TFR(24)  x0 += kx; x1 += k0 + 2u;
    TFR(13) TFR(15) TFR(26) TFR(6)   x0 += k0; x1 += k1 + 3u;
    TFR(17) TFR(29) TFR(16) TFR(24)  x0 += k1; x1 += kx + 4u;
    TFR(13) TFR(15) TFR(26) TFR(6)   x0 += kx; x1 += k0 + 5u;
#undef TFR
    o0 = x0; o1 = x1;
}

// XLA f32 ErfInv (Giles)
__device__ __forceinline__ float erfinv_xla(float x) {
    float w = -log1pf(-x * x);
    float p;
    if (w < 5.f) {
        w -= 2.5f;
        p = 2.81022636e-08f;
        p = fmaf(p, w, 3.43273939e-07f);
        p = fmaf(p, w, -3.5233877e-06f);
        p = fmaf(p, w, -4.39150654e-06f);
        p = fmaf(p, w, 0.00021858087f);
        p = fmaf(p, w, -0.00125372503f);
        p = fmaf(p, w, -0.00417768164f);
        p = fmaf(p, w, 0.246640727f);
        p = fmaf(p, w, 1.50140941f);
    } else {
        w = sqrtf(w) - 3.f;
        p = -0.000200214257f;
        p = fmaf(p, w, 0.000100950558f);
        p = fmaf(p, w, 0.00134934322f);
        p = fmaf(p, w, -0.00367342844f);
        p = fmaf(p, w, 0.00573950773f);
        p = fmaf(p, w, -0.0076224613f);
        p = fmaf(p, w, 0.00943887047f);
        p = fmaf(p, w, 1.00167406f);
        p = fmaf(p, w, 2.83297682f);
    }
    return p * x;
}

__device__ __forceinline__ float jax_normal(uint32_t k0, uint32_t k1, uint32_t idx) {
    uint32_t o0, o1;
    tf2x32(k0, k1, 0u, idx, o0, o1);
    uint32_t bits = o0 ^ o1;
    float f = __uint_as_float((bits >> 9) | 0x3f800000u) - 1.0f;
    const float lo = -0.99999994f;   // nextafter(-1,0)
    float val = fmaxf(fmaf(f, 2.0f, lo), lo);
    return 1.4142135623730951f * erfinv_xla(val);
}

// ---------------- sync primitives ----------------
__device__ __forceinline__ void st_release(unsigned* p, unsigned v) {
    asm volatile("st.release.gpu.global.u32 [%0], %1;" :: "l"(p), "r"(v) : "memory");
}
__device__ __forceinline__ unsigned ld_acquire(const unsigned* p) {
    unsigned v;
    asm volatile("ld.acquire.gpu.global.u32 %0, [%1];" : "=r"(v) : "l"(p) : "memory");
    return v;
}

// ---------------- main persistent RNN kernel ----------------
__global__ void __launch_bounds__(256, 1)
rnn_main(const float* __restrict__ i_stim, const float* __restrict__ i_cc,
         const float* __restrict__ hidden, const float* __restrict__ w_ih,
         const float* __restrict__ w_hh, const float* __restrict__ b_hh,
         const float* __restrict__ w_ho,
         float* __restrict__ hids) {
    __shared__ __align__(16) float rh_s[NW][NB][KW];  // per-warp staged slices (4 KB)
    __shared__ float red_s[2][NW][NB][NJC];           // double-buffered partials (16 KB)
    __shared__ float cur_s[2][NB][2];                 // relu(x + in-noise), 2-deep

    const int tid = threadIdx.x;
    const int w = tid >> 5, l = tid & 31;
    const int jg = blockIdx.x, bg = blockIdx.y;
    const int J0 = jg * NJC, B0 = bg * NB;
    // GEMM role: lane l covers j1 = J0+l and j2 = J0+32+l over k-range [64w, 64w+64)
    const int j1 = J0 + l, j2 = J0 + 32 + l;
    const int k0 = w * KW;
    // epilogue role: (batch = w>>1, j = (w&1)*32 + l)
    const int be = w >> 1, jl = ((w & 1) << 5) + l;
    const int bglob = B0 + be, jglob = J0 + jl;

    uint32_t kin0, kin1, krec0, krec1;
    tf2x32(0u, 42u, 0u, 0u, kin0, kin1);
    tf2x32(0u, 42u, 0u, 1u, krec0, krec1);

    // Time-invariant W_ei chunks for the lane's two j rows, packed f32x2:
    // w_ei[j][k] = abs(w_hh[j][k]) * (k==j ? 0 : (k<409 ? +1 : -1))
    unsigned long long wpa[KW / 2], wpb[KW / 2];
#pragma unroll
    for (int i = 0; i < KW / 2; i++) {
        int k = k0 + 2 * i;
        float a0 = fabsf(w_hh[j1 * HID + k]);
        float a1 = fabsf(w_hh[j1 * HID + k + 1]);
        float b0 = fabsf(w_hh[j2 * HID + k]);
        float b1 = fabsf(w_hh[j2 * HID + k + 1]);
        if (k == j1) a0 = 0.f;
        if (k + 1 == j1) a1 = 0.f;
        if (k == j2) b0 = 0.f;
        if (k + 1 == j2) b1 = 0.f;
        if (k >= NEXC) { a0 = -a0; b0 = -b0; }
        if (k + 1 >= NEXC) { a1 = -a1; b1 = -b1; }
        asm("mov.b64 %0, {%1, %2};" : "=l"(wpa[i]) : "f"(a0), "f"(a1));
        asm("mov.b64 %0, {%1, %2};" : "=l"(wpb[i]) : "f"(b0), "f"(b1));
    }

    const float wih0 = w_ih[jglob * 2];
    const float wih1 = w_ih[jglob * 2 + 1];
    const float bhh  = b_hh[jglob];
    const float who  = w_ho[jglob];
    float hreg = hidden[bglob * HID + jglob];

    // ---- prologue: noise + currents for step 0 computed up front ----
    float nr = jax_normal(krec0, krec1, (uint32_t)((0 * BATCH + bglob) * HID + jglob));
    if (tid < NB * 2) {
        int bb = tid >> 1, ii = tid & 1;
        int bB = B0 + bb;
        float x = (ii == 0 ? i_stim : i_cc)[bB * TSTEPS + 0];
        float n = jax_normal(kin0, kin1, (uint32_t)((0 * BATCH + bB) * 2 + ii));
        cur_s[0][bb][ii] = fmaxf(fmaf(IN_SCALE_F, n, x), 0.f);
    }

    // publish relu(h0) into buffer 0, then announce
    __stcg(&g_h[0][bglob * HID + jglob], fmaxf(hreg, 0.f));
    __syncthreads();
    if (tid == 0) st_release(&g_flag[bg][jg][0], 1u);

    // per-warp poll: ONE producer CTA (jg' = w); lane 0 polls
    const unsigned* fpoll = &g_flag[bg][w][0];
    // staging role: lane l -> (b = l>>4 and +2, float4 col = l&15)
    const int sb = l >> 4, sc = l & 15;

    for (int t = 0; t < TSTEPS; t++) {
        const int rb = t & 1, wb = rb ^ 1;
        const unsigned tgt = (unsigned)(t + 1);

        // --- per-warp wait on THIS warp's single producer CTA (nothing ahead
        // of it: noise/currents for this step were computed last step) ---
        for (;;) {
            unsigned v = (l == 0) ? ld_acquire(fpoll) : tgt;
            if (__all_sync(0xffffffffu, v >= tgt)) break;
        }

        // --- stage this warp's slice (already relu'd by producers): 4b x 64k ---
        {
            const float* src = &g_h[rb][B0 * HID + k0];
#pragma unroll
            for (int q = 0; q < 2; q++) {
                const int b = q * 2 + sb;
                float4 v = __ldcg((const float4*)(src + b * HID + sc * 4));
                *(float4*)&rh_s[w][b][sc * 4] = v;
            }
        }
        __syncwarp();

        // --- GEMM partials: each rh load feeds BOTH j rows (2x FMA per LDS) ---
        unsigned long long acc2a[NB], acc2b[NB];
#pragma unroll
        for (int b = 0; b < NB; b++) { acc2a[b] = 0ull; acc2b[b] = 0ull; }
#pragma unroll
        for (int kk = 0; kk < KW; kk += 4) {
            const unsigned long long wa01 = wpa[kk / 2];
            const unsigned long long wa23 = wpa[kk / 2 + 1];
            const unsigned long long wb01 = wpb[kk / 2];
            const unsigned long long wb23 = wpb[kk / 2 + 1];
#pragma unroll
            for (int b = 0; b < NB; b++) {
                unsigned long long r01, r23;
                uint32_t a = (uint32_t)__cvta_generic_to_shared(&rh_s[w][b][kk]);
                asm("ld.shared.v2.u64 {%0, %1}, [%2];"
                    : "=l"(r01), "=l"(r23) : "r"(a));   // broadcast LDS.128
                asm("fma.rn.f32x2 %0, %1, %2, %0;" : "+l"(acc2a[b]) : "l"(r01), "l"(wa01));
                asm("fma.rn.f32x2 %0, %1, %2, %0;" : "+l"(acc2a[b]) : "l"(r23), "l"(wa23));
                asm("fma.rn.f32x2 %0, %1, %2, %0;" : "+l"(acc2b[b]) : "l"(r01), "l"(wb01));
                asm("fma.rn.f32x2 %0, %1, %2, %0;" : "+l"(acc2b[b]) : "l"(r23), "l"(wb23));
            }
        }
#pragma unroll
        for (int b = 0; b < NB; b++) {
            float lo, hi;
            asm("mov.b64 {%0, %1}, %2;" : "=f"(lo), "=f"(hi) : "l"(acc2a[b]));
            red_s[rb][w][b][l] = lo + hi;
            asm("mov.b64 {%0, %1}, %2;" : "=f"(lo), "=f"(hi) : "l"(acc2b[b]));
            red_s[rb][w][b][32 + l] = lo + hi;
        }
        __syncthreads();   // sync #1: red handoff

        // --- epilogue: integrate h for (bglob, jglob) ---
        float s = 0.f;
#pragma unroll
        for (int ww = 0; ww < NW; ww++) s += red_s[rb][ww][be][jl];
        float hid_in  = fmaf(cur_s[rb][be][0], wih0, cur_s[rb][be][1] * wih1);
        float hid_hid = s + bhh + REC_SCALE_F * nr;
        float h = hreg;
        float hn = fmaf(hid_in + hid_hid - h, ALPHA_F, h);
        hreg = hn;
        __stcg(&g_h[wb][bglob * HID + jglob], fmaxf(hn, 0.f));
        __syncthreads();   // sync #2: all h stores done before the release
        if (tid == 0) st_release(&g_flag[bg][jg][0], (unsigned)(t + 2));

        // --- post-release SHADOW region: consumers are busy discovering our
        // flag (~300-500 cyc). Do all off-path work for step t AND prefetch
        // next step's noise/currents here so the next iteration polls instantly.
        __stcs(&hids[(size_t)bglob * (TSTEPS * HID) + (size_t)t * HID + jglob], hn);
        float op = fmaxf(hn, 0.f) * who;
#pragma unroll
        for (int o = 16; o; o >>= 1) op += __shfl_down_sync(0xffffffffu, op, o);
        if (l == 0)
            g_opart[((size_t)bglob * TSTEPS + t) * GJP + jg * 2 + (w & 1)] = op;

        if (t + 1 < TSTEPS) {
            const int tn = t + 1;
            nr = jax_normal(krec0, krec1,
                            (uint32_t)((tn * BATCH + bglob) * HID + jglob));
            if (tid < NB * 2) {
                int bb = tid >> 1, ii = tid & 1;
                int bB = B0 + bb;
                float x = (ii == 0 ? i_stim : i_cc)[bB * TSTEPS + tn];
                float n = jax_normal(kin0, kin1,
                                     (uint32_t)((tn * BATCH + bB) * 2 + ii));
                cur_s[wb][bb][ii] = fmaxf(fmaf(IN_SCALE_F, n, x), 0.f);
            }
        }
    }
}

// ---------------- output: sum 16 partials + bias ----------------
__global__ void out_kernel(const float* __restrict__ b_ho, float* __restrict__ outs) {
    int i = blockIdx.x * blockDim.x + threadIdx.x;   // i = b*T + t
    if (i >= BATCH * TSTEPS) return;
    const float4* p = (const float4*)&g_opart[(size_t)i * GJP];
    float s = 0.f;
#pragma unroll
    for (int q = 0; q < GJP / 4; q++) {
        float4 v = p[q];
        s += (v.x + v.y) + (v.z + v.w);
    }
    outs[i] = s + b_ho[0];
}

// ---------------- launch ----------------
extern "C" void kernel_launch(void* const* d_in, const int* in_sizes, int n_in,
                              void* d_out, int out_size) {
    const float* i_stim = (const float*)d_in[0];
    const float* i_cc   = (const float*)d_in[1];
    const float* hidden = (const float*)d_in[2];
    const float* w_ih   = (const float*)d_in[3];
    // d_in[4] = b_ih — never used by the reference (faithful to source)
    const float* w_hh   = (const float*)d_in[5];
    const float* b_hh   = (const float*)d_in[6];
    const float* w_ho   = (const float*)d_in[7];
    const float* b_ho   = (const float*)d_in[8];

    float* outs = (float*)d_out;                 // [B,T,1]
    float* hids = outs + (size_t)BATCH * TSTEPS; // [B,T,H]

    void* flagp = nullptr;
    cudaGetSymbolAddress(&flagp, g_flag);
    cudaMemsetAsync(flagp, 0, sizeof(unsigned) * GB * GJ * 32);

    dim3 grid(GJ, GB);
    rnn_main<<<grid, 256>>>(i_stim, i_cc, hidden, w_ih, w_hh, b_hh, w_ho, hids);

    int blocks = (BATCH * TSTEPS + 255) / 256;
    out_kernel<<<blocks, 256>>>(b_ho, outs);
}